// round 10
// baseline (speedup 1.0000x reference)
#include <cuda_runtime.h>
#include <cuda_fp16.h>
#include <cstdint>
#include <math.h>

#define B_  128
#define F_  1024
#define W_  32
#define H_  64
#define G_  256
#define NCH 64           // total k16 chunks
#define NIT 32           // chunks per k-half (per warp)

#define AP  40           // A smem row pitch (fp16): conflict-free ldmatrix
#define SMEM_GEMM (F_ * AP * 2)   // 81920 B

using u64 = unsigned long long;

// B pre-packed fp16 hi/lo mma fragments: [chunk][ntile][lane] -> uint4{bh0,bh1,bl0,bl1}
__device__ uint4 g_wxp[NCH * 32 * 32];
// Gate tile: [b][t][g]  (4 MB)
__device__ float g_gate[B_ * W_ * G_];

__device__ __forceinline__ uint32_t smem_u32(const void* p) {
    return (uint32_t)__cvta_generic_to_shared(p);
}
__device__ __forceinline__ void ldm4t(uint32_t* r, uint32_t addr) {
    asm volatile("ldmatrix.sync.aligned.m8n8.x4.trans.shared.b16 {%0,%1,%2,%3}, [%4];"
                 : "=r"(r[0]), "=r"(r[1]), "=r"(r[2]), "=r"(r[3]) : "r"(addr));
}
__device__ __forceinline__ void mma_f16(float* d, const uint32_t* a, uint32_t b0, uint32_t b1) {
    asm volatile("mma.sync.aligned.m16n8k16.row.col.f32.f16.f16.f32 "
                 "{%0,%1,%2,%3}, {%4,%5,%6,%7}, {%8,%9}, {%0,%1,%2,%3};"
                 : "+f"(d[0]), "+f"(d[1]), "+f"(d[2]), "+f"(d[3])
                 : "r"(a[0]), "r"(a[1]), "r"(a[2]), "r"(a[3]), "r"(b0), "r"(b1));
}
__device__ __forceinline__ u64 fma2(u64 a, u64 b, u64 c) {
    u64 d; asm("fma.rn.f32x2 %0, %1, %2, %3;" : "=l"(d) : "l"(a), "l"(b), "l"(c)); return d;
}
__device__ __forceinline__ u64 add2(u64 a, u64 b) {
    u64 d; asm("add.rn.f32x2 %0, %1, %2;" : "=l"(d) : "l"(a), "l"(b)); return d;
}
__device__ __forceinline__ u64 pack2(float lo, float hi) {
    u64 d; asm("mov.b64 %0, {%1, %2};" : "=l"(d)
               : "r"(__float_as_uint(lo)), "r"(__float_as_uint(hi)));
    return d;
}
__device__ __forceinline__ float2 unpack2(u64 a) {
    unsigned lo, hi; asm("mov.b64 {%0, %1}, %2;" : "=r"(lo), "=r"(hi) : "l"(a));
    return make_float2(__uint_as_float(lo), __uint_as_float(hi));
}
__device__ __forceinline__ uint32_t packh(float a, float b) {
    __half2 h = __floats2half2_rn(a, b);
    return *(uint32_t*)&h;
}

// ---------------------------------------------------------------------------
// Pre-kernel: Wx fp32 -> packed fp16 hi/lo mma B-fragments, via smem staging.
// ---------------------------------------------------------------------------
extern "C" __global__ void __launch_bounds__(256)
conv_wx_kernel(const float* __restrict__ Wx)
{
    __shared__ float sw[32 * 256];
    const int b2  = blockIdx.x;
    const int tid = threadIdx.x;

    const float* src = Wx + (size_t)b2 * 32 * G_;
#pragma unroll
    for (int seg = 0; seg < 8; ++seg) {
        int i = (seg * 256 + tid) * 4;
        *(float4*)(sw + i) = *(const float4*)(src + i);
    }
    __syncthreads();

#pragma unroll
    for (int e = 0; e < 8; ++e) {
        int ent   = e * 256 + tid;
        int cloc  = ent >> 10;
        int tile  = (ent >> 5) & 31;
        int lane  = ent & 31;
        int n     = tile * 8 + (lane >> 2);
        int k0    = cloc * 16 + 2 * (lane & 3);

        float w00 = sw[(k0    ) * G_ + n];
        float w01 = sw[(k0 + 1) * G_ + n];
        float w10 = sw[(k0 + 8) * G_ + n];
        float w11 = sw[(k0 + 9) * G_ + n];

        float h00 = __half2float(__float2half_rn(w00));
        float h01 = __half2float(__float2half_rn(w01));
        float h10 = __half2float(__float2half_rn(w10));
        float h11 = __half2float(__float2half_rn(w11));

        uint4 v;
        v.x = packh(h00, h01);
        v.y = packh(h10, h11);
        v.z = packh(w00 - h00, w01 - h01);
        v.w = packh(w10 - h10, w11 - h11);
        g_wxp[(size_t)b2 * 2048 + ent] = v;
    }
}

// ---------------------------------------------------------------------------
// GEMM kernel: grid (128 batches, 2 n-halves), 256 threads (8 warps).
//  gate[b, t, nh*128 + j] = sum_f x[b,f,t] * Wx[f, nh*128 + j]
//  (softmax over the size-1 axis == 1 -> attention branch is dead code)
//  fp16 one-sided split-2: a*bh + a*bl, a = fp16(x).
//  Warp (kg = w>>2, wn = w&3): m32 x n32 at col 128nh+32wn over k-half kg.
//  A (full, fp16) staged once (80 KB); B frags direct LDG.128, prefetched.
//  2 CTAs/SM -> all 256 CTAs resident; no cross-CTA reduction (n-split).
// ---------------------------------------------------------------------------
extern "C" __global__ void __launch_bounds__(256, 2)
xproj_gemm(const float* __restrict__ x)
{
    extern __shared__ __align__(16) __half sA[];   // [F_][AP]; later gate half tile

    const int b    = blockIdx.x;
    const int nh   = blockIdx.y;
    const int tid  = threadIdx.x;
    const int w    = tid >> 5;
    const int lane = tid & 31;
    const int kg   = w >> 2;      // k-half
    const int wn   = w & 3;       // n-group within half

    const float* xb = x + (size_t)b * F_ * W_;

    // ---- stage full A (fp16) ----
    {
        const int rbase = tid >> 4;           // 0..15
        const int tc    = (tid & 15) * 2;
#pragma unroll 4
        for (int seg = 0; seg < 64; ++seg) {
            int f = rbase + 16 * seg;
            float2 v = *(const float2*)(xb + (size_t)f * W_ + tc);
            *(__half2*)(sA + f * AP + tc) = __floats2half2_rn(v.x, v.y);
        }
    }
    __syncthreads();

    float acc[2][4][4];
#pragma unroll
    for (int mt = 0; mt < 2; ++mt)
#pragma unroll
        for (int j = 0; j < 4; ++j)
#pragma unroll
            for (int i = 0; i < 4; ++i) acc[mt][j][i] = 0.f;

    const int lr = lane & 7, lg = lane >> 3;
    const int akq = (lg & 2) ? (8 + lr) : lr;
    const int amo = (lg & 1) ? 8 : 0;

    // B source: this warp's 4 n-tiles start at global tile 16*nh + 4*wn
    const uint4* bsrc = g_wxp + ((size_t)(16 * nh + 4 * wn) * 32) + lane;
    const int ch0 = kg * NIT;

    uint4 bq[4], bq_n[4];
#pragma unroll
    for (int j = 0; j < 4; ++j)
        bq[j] = bsrc[(size_t)ch0 * 1024 + (size_t)j * 32];

    for (int c = 0; c < NIT; ++c) {
        int cn = (c + 1 < NIT) ? (ch0 + c + 1) : (ch0 + c);
#pragma unroll
        for (int j = 0; j < 4; ++j)
            bq_n[j] = bsrc[(size_t)cn * 1024 + (size_t)j * 32];

        int fb = (ch0 + c) * 16 + akq;
        uint32_t ah[2][4];
#pragma unroll
        for (int mt = 0; mt < 2; ++mt)
            ldm4t(ah[mt], smem_u32(sA + fb * AP + 16 * mt + amo));

#pragma unroll
        for (int j = 0; j < 4; ++j) {
#pragma unroll
            for (int mt = 0; mt < 2; ++mt) {
                mma_f16(acc[mt][j], ah[mt], bq[j].x, bq[j].y);   // a*bh
                mma_f16(acc[mt][j], ah[mt], bq[j].z, bq[j].w);   // a*bl
            }
        }
#pragma unroll
        for (int j = 0; j < 4; ++j) bq[j] = bq_n[j];
    }
    __syncthreads();     // done reading A

    // ---- split-K-2 reduction into gate half tile [32][128] (reuses sA) ----
    float* xp = (float*)sA;
    const int r0 = lane >> 2, c0 = 2 * (lane & 3);
    if (kg == 1) {
#pragma unroll
        for (int mt = 0; mt < 2; ++mt)
#pragma unroll
            for (int j = 0; j < 4; ++j) {
                int n = 32 * wn + 8 * j;
                *(float2*)(xp + (16 * mt + r0) * 128 + n + c0)     = make_float2(acc[mt][j][0], acc[mt][j][1]);
                *(float2*)(xp + (16 * mt + r0 + 8) * 128 + n + c0) = make_float2(acc[mt][j][2], acc[mt][j][3]);
            }
    }
    __syncthreads();
    if (kg == 0) {
#pragma unroll
        for (int mt = 0; mt < 2; ++mt)
#pragma unroll
            for (int j = 0; j < 4; ++j) {
                int n = 32 * wn + 8 * j;
                float2* p0 = (float2*)(xp + (16 * mt + r0) * 128 + n + c0);
                float2* p1 = (float2*)(xp + (16 * mt + r0 + 8) * 128 + n + c0);
                float2 v0 = *p0, v1 = *p1;
                *p0 = make_float2(v0.x + acc[mt][j][0], v0.y + acc[mt][j][1]);
                *p1 = make_float2(v1.x + acc[mt][j][2], v1.y + acc[mt][j][3]);
            }
    }
    __syncthreads();

    // ---- coalesced store to global gate buffer ----
    float* gdst = g_gate + (size_t)b * W_ * G_ + 128 * nh;
#pragma unroll
    for (int i = tid * 4; i < W_ * 128; i += 256 * 4) {
        int row = i >> 7, col = i & 127;
        *(float4*)(gdst + row * G_ + col) = *(float4*)(xp + i);
    }
}

// ---------------------------------------------------------------------------
// LSTM kernel: grid 128, 256 threads. Stage gate tile, run recurrence.
// Output per step = CELL state (reference's s/h swap).
// ---------------------------------------------------------------------------
extern "C" __global__ void __launch_bounds__(256, 1)
lstm_kernel(const float* __restrict__ Wh, const float* __restrict__ b_lstm,
            float* __restrict__ out)
{
    __shared__ __align__(16) float xp[W_ * G_];    // 32 KB
    __shared__ __align__(16) float h_s[2][H_];

    const int b    = blockIdx.x;
    const int tid  = threadIdx.x;
    const int w    = tid >> 5;
    const int lane = tid & 31;

    // stage gate tile (coalesced)
    {
        const float* src = g_gate + (size_t)b * W_ * G_;
#pragma unroll
        for (int i = tid * 4; i < W_ * G_; i += 256 * 4)
            *(float4*)(xp + i) = *(const float4*)(src + i);
    }

    const int q   = lane >> 3;
    const int r   = lane & 7;
    const int idx = 8 * w + r;
    const int col = q * 64 + idx;

    u64 whp[H_ / 2];
#pragma unroll
    for (int m = 0; m < H_ / 2; ++m)
        whp[m] = pack2(Wh[(2 * m) * G_ + col], Wh[(2 * m + 1) * G_ + col]);
    const float bj = b_lstm[col];

    if (tid < H_) h_s[0][tid] = 0.f;
    float c_st = 0.f;
    float* ob = out + (size_t)b * W_ * H_;
    __syncthreads();

    int p = 0;
    for (int t = 0; t < W_; ++t) {
        const u64* hp = (const u64*)h_s[p];
        u64 a0 = 0ull, a1 = 0ull, a2 = 0ull, a3 = 0ull;
#pragma unroll
        for (int m = 0; m < H_ / 2; m += 4) {
            a0 = fma2(hp[m + 0], whp[m + 0], a0);
            a1 = fma2(hp[m + 1], whp[m + 1], a1);
            a2 = fma2(hp[m + 2], whp[m + 2], a2);
            a3 = fma2(hp[m + 3], whp[m + 3], a3);
        }
        float2 s2 = unpack2(add2(add2(a0, a1), add2(a2, a3)));
        float g = s2.x + s2.y + xp[t * G_ + col] + bj;

        float sc  = (q == 2) ? -2.f : -1.f;
        float e   = __expf(sc * g);
        float num = (q == 2) ? (1.f - e) : 1.f;
        float act = __fdividef(num, 1.f + e);

        float ai = __shfl_sync(0xffffffffu, act, r);
        float af = __shfl_sync(0xffffffffu, act, 8 + r);
        float ag = __shfl_sync(0xffffffffu, act, 16 + r);
        float ao = __shfl_sync(0xffffffffu, act, 24 + r);

        c_st = fmaf(af, c_st, ai * ag);
        float e2 = __expf(-2.f * c_st);
        float th = __fdividef(1.f - e2, 1.f + e2);

        if (q == 0) {
            h_s[p ^ 1][idx] = ao * th;
            ob[t * H_ + idx] = c_st;              // reference emits the CELL state
        }
        p ^= 1;
        __syncthreads();
    }
}

// ---------------------------------------------------------------------------
extern "C" void kernel_launch(void* const* d_in, const int* in_sizes, int n_in,
                              void* d_out, int out_size)
{
    const float* x      = (const float*)d_in[0];
    const float* Wx     = (const float*)d_in[6];
    const float* Wh     = (const float*)d_in[7];
    const float* b_lstm = (const float*)d_in[8];
    float*       out    = (float*)d_out;

    cudaFuncSetAttribute(xproj_gemm, cudaFuncAttributeMaxDynamicSharedMemorySize, SMEM_GEMM);

    conv_wx_kernel<<<32, 256>>>(Wx);
    xproj_gemm<<<dim3(B_, 2), 256, SMEM_GEMM>>>(x);
    lstm_kernel<<<B_, 256>>>(Wh, b_lstm, out);
}

// round 11
// speedup vs baseline: 1.3861x; 1.3861x over previous
#include <cuda_runtime.h>
#include <cuda_fp16.h>
#include <cstdint>
#include <math.h>

#define B_  128
#define F_  1024
#define W_  32
#define H_  64
#define G_  256
#define NCH 64           // total k16 chunks
#define NIT 32           // chunks per k-half (per warp group)

#define AP  40           // A smem row pitch (fp16): conflict-free ldmatrix
#define SMEM_DYN (F_ * AP * 2)   // 81920 B

using u64 = unsigned long long;

// B pre-packed fp16 mma fragments: [chunk][ntile][lane] -> uint2{b0,b1}
__device__ uint2 g_wxp[NCH * 32 * 32];

__device__ __forceinline__ uint32_t smem_u32(const void* p) {
    return (uint32_t)__cvta_generic_to_shared(p);
}
__device__ __forceinline__ void ldm4t(uint32_t* r, uint32_t addr) {
    asm volatile("ldmatrix.sync.aligned.m8n8.x4.trans.shared.b16 {%0,%1,%2,%3}, [%4];"
                 : "=r"(r[0]), "=r"(r[1]), "=r"(r[2]), "=r"(r[3]) : "r"(addr));
}
__device__ __forceinline__ void mma_f16(float* d, const uint32_t* a, uint32_t b0, uint32_t b1) {
    asm volatile("mma.sync.aligned.m16n8k16.row.col.f32.f16.f16.f32 "
                 "{%0,%1,%2,%3}, {%4,%5,%6,%7}, {%8,%9}, {%0,%1,%2,%3};"
                 : "+f"(d[0]), "+f"(d[1]), "+f"(d[2]), "+f"(d[3])
                 : "r"(a[0]), "r"(a[1]), "r"(a[2]), "r"(a[3]), "r"(b0), "r"(b1));
}
__device__ __forceinline__ u64 fma2(u64 a, u64 b, u64 c) {
    u64 d; asm("fma.rn.f32x2 %0, %1, %2, %3;" : "=l"(d) : "l"(a), "l"(b), "l"(c)); return d;
}
__device__ __forceinline__ u64 add2(u64 a, u64 b) {
    u64 d; asm("add.rn.f32x2 %0, %1, %2;" : "=l"(d) : "l"(a), "l"(b)); return d;
}
__device__ __forceinline__ u64 pack2(float lo, float hi) {
    u64 d; asm("mov.b64 %0, {%1, %2};" : "=l"(d)
               : "r"(__float_as_uint(lo)), "r"(__float_as_uint(hi)));
    return d;
}
__device__ __forceinline__ float2 unpack2(u64 a) {
    unsigned lo, hi; asm("mov.b64 {%0, %1}, %2;" : "=r"(lo), "=r"(hi) : "l"(a));
    return make_float2(__uint_as_float(lo), __uint_as_float(hi));
}
__device__ __forceinline__ uint32_t packh(float a, float b) {
    __half2 h = __floats2half2_rn(a, b);       // low = a, high = b
    return *(uint32_t*)&h;
}

// ---------------------------------------------------------------------------
// Pre-kernel: Wx fp32 -> packed fp16 mma B-fragments. One block per k16
// chunk (grid 64): stage 16 rows x 256 cols (16 KB), emit 1024 uint2 entries.
// ---------------------------------------------------------------------------
extern "C" __global__ void __launch_bounds__(256)
conv_wx_kernel(const float* __restrict__ Wx)
{
    __shared__ float sw[16 * 256];
    const int ch  = blockIdx.x;
    const int tid = threadIdx.x;

    const float* src = Wx + (size_t)ch * 16 * G_;
#pragma unroll
    for (int seg = 0; seg < 4; ++seg) {
        int i = (seg * 256 + tid) * 4;
        *(float4*)(sw + i) = *(const float4*)(src + i);
    }
    __syncthreads();

#pragma unroll
    for (int e = 0; e < 4; ++e) {
        int ent   = e * 256 + tid;          // 0..1023
        int tile  = ent >> 5;
        int lane  = ent & 31;
        int n     = tile * 8 + (lane >> 2);
        int k0    = 2 * (lane & 3);

        uint2 v;
        v.x = packh(sw[(k0    ) * G_ + n], sw[(k0 + 1) * G_ + n]);
        v.y = packh(sw[(k0 + 8) * G_ + n], sw[(k0 + 9) * G_ + n]);
        g_wxp[(size_t)ch * 1024 + ent] = v;
    }
}

// ---------------------------------------------------------------------------
// Fused kernel: 1 block per batch, 512 threads (16 warps).
//  Prologue: stage full A (x[b] as fp16) into smem once (80 KB).
//  Phase 1: barrier-free fp16 GEMM:
//    Xp[t,g] = sum_f x[b,f,t]*Wx[f,g]  (both operands fp16, fp32 accum;
//    analytic rel err ~4e-4, under the 1e-3 gate)
//   (softmax over the size-1 axis == 1 -> attention branch is dead code)
//   Warp (kg=w>>3, wn=w&7): m32 x n32 at n0=32wn over k-half kg.
//   BOTH operands prefetched one chunk ahead: A frags via ldmatrix
//   ping-pong, B frags via direct LDG.64 from the packed array.
//   Split-K-2 smem reduction into gate tile (reuses A region).
//  Phase 2: LSTM recurrence on warps 0-7; output = CELL state.
// ---------------------------------------------------------------------------
extern "C" __global__ void __launch_bounds__(512, 1)
attn_rnn_tc(const float* __restrict__ x,  const float* __restrict__ Wh,
            const float* __restrict__ b_lstm, float* __restrict__ out)
{
    extern __shared__ __align__(16) __half sA[];   // [F_][AP] fp16 ; later gate tile
    __shared__ __align__(16) float h_s[2][H_];

    const int b    = blockIdx.x;
    const int tid  = threadIdx.x;
    const int w    = tid >> 5;
    const int lane = tid & 31;
    const int kg   = w >> 3;      // k-half
    const int wn   = w & 7;       // n-group

    const float* xb = x + (size_t)b * F_ * W_;

    // ---- Prologue: stage all of A (fp16) ----
    {
        const int rbase = tid >> 4;           // 0..31
        const int tc    = (tid & 15) * 2;     // t column pair
#pragma unroll 4
        for (int seg = 0; seg < 32; ++seg) {
            int f = rbase + 32 * seg;
            float2 v = *(const float2*)(xb + (size_t)f * W_ + tc);
            *(__half2*)(sA + f * AP + tc) = __floats2half2_rn(v.x, v.y);
        }
    }
    __syncthreads();

    float acc[2][4][4];
#pragma unroll
    for (int mt = 0; mt < 2; ++mt)
#pragma unroll
        for (int j = 0; j < 4; ++j)
#pragma unroll
            for (int i = 0; i < 4; ++i) acc[mt][j][i] = 0.f;

    // ldmatrix lane addressing (within a chunk)
    const int lr = lane & 7, lg = lane >> 3;
    const int akq = (lg & 2) ? (8 + lr) : lr;
    const int amo = (lg & 1) ? 8 : 0;

    // B source: chunk-major; this warp's 4 n-tiles start at tile 4*wn
    const uint2* bsrc = g_wxp + ((size_t)(4 * wn) * 32) + lane;
    const int ch0 = kg * NIT;

    uint2 bq[4], bq_n[4];
    uint32_t ahc[2][4], ahn[2][4];
#pragma unroll
    for (int j = 0; j < 4; ++j)
        bq[j] = bsrc[(size_t)ch0 * 1024 + (size_t)j * 32];
    {
        int fb = ch0 * 16 + akq;
#pragma unroll
        for (int mt = 0; mt < 2; ++mt)
            ldm4t(ahc[mt], smem_u32(sA + fb * AP + 16 * mt + amo));
    }

    for (int c = 0; c < NIT; ++c) {
        int cn = (c + 1 < NIT) ? (ch0 + c + 1) : (ch0 + c);   // clamp last prefetch
#pragma unroll
        for (int j = 0; j < 4; ++j)
            bq_n[j] = bsrc[(size_t)cn * 1024 + (size_t)j * 32];
        {
            int fb = cn * 16 + akq;
#pragma unroll
            for (int mt = 0; mt < 2; ++mt)
                ldm4t(ahn[mt], smem_u32(sA + fb * AP + 16 * mt + amo));
        }

#pragma unroll
        for (int j = 0; j < 4; ++j)
#pragma unroll
            for (int mt = 0; mt < 2; ++mt)
                mma_f16(acc[mt][j], ahc[mt], bq[j].x, bq[j].y);

#pragma unroll
        for (int j = 0; j < 4; ++j) bq[j] = bq_n[j];
#pragma unroll
        for (int mt = 0; mt < 2; ++mt)
#pragma unroll
            for (int i = 0; i < 4; ++i) ahc[mt][i] = ahn[mt][i];
    }
    __syncthreads();     // all warps done reading A before gate tile overwrites it

    // ---- split-K-2 reduction into gate tile [32][256] fp32 ----
    float* xp = (float*)sA;
    const int r0 = lane >> 2, c0 = 2 * (lane & 3);
    if (kg == 1) {
#pragma unroll
        for (int mt = 0; mt < 2; ++mt)
#pragma unroll
            for (int j = 0; j < 4; ++j) {
                int n = 32 * wn + 8 * j;
                *(float2*)(xp + (16 * mt + r0) * G_ + n + c0)     = make_float2(acc[mt][j][0], acc[mt][j][1]);
                *(float2*)(xp + (16 * mt + r0 + 8) * G_ + n + c0) = make_float2(acc[mt][j][2], acc[mt][j][3]);
            }
    }
    __syncthreads();
    if (kg == 0) {
#pragma unroll
        for (int mt = 0; mt < 2; ++mt)
#pragma unroll
            for (int j = 0; j < 4; ++j) {
                int n = 32 * wn + 8 * j;
                float2* p0 = (float2*)(xp + (16 * mt + r0) * G_ + n + c0);
                float2* p1 = (float2*)(xp + (16 * mt + r0 + 8) * G_ + n + c0);
                float2 v0 = *p0, v1 = *p1;
                *p0 = make_float2(v0.x + acc[mt][j][0], v0.y + acc[mt][j][1]);
                *p1 = make_float2(v1.x + acc[mt][j][2], v1.y + acc[mt][j][3]);
            }
    }
    __syncthreads();

    // ---------------- Phase 2: LSTM recurrence (warps 0-7 only) ----------------
    if (tid >= 256) return;

    const int q   = lane >> 3;
    const int r   = lane & 7;
    const int idx = 8 * w + r;
    const int col = q * 64 + idx;

    u64 whp[H_ / 2];
#pragma unroll
    for (int m = 0; m < H_ / 2; ++m)
        whp[m] = pack2(Wh[(2 * m) * G_ + col], Wh[(2 * m + 1) * G_ + col]);
    const float bj = b_lstm[col];

    if (tid < H_) h_s[0][tid] = 0.f;
    float c_st = 0.f;
    float* ob = out + (size_t)b * W_ * H_;
    asm volatile("bar.sync 1, 256;" ::: "memory");

    int p = 0;
    for (int t = 0; t < W_; ++t) {
        const u64* hp = (const u64*)h_s[p];
        u64 a0 = 0ull, a1 = 0ull, a2 = 0ull, a3 = 0ull;
#pragma unroll
        for (int m = 0; m < H_ / 2; m += 4) {
            a0 = fma2(hp[m + 0], whp[m + 0], a0);
            a1 = fma2(hp[m + 1], whp[m + 1], a1);
            a2 = fma2(hp[m + 2], whp[m + 2], a2);
            a3 = fma2(hp[m + 3], whp[m + 3], a3);
        }
        float2 s2 = unpack2(add2(add2(a0, a1), add2(a2, a3)));
        float g = s2.x + s2.y + xp[t * G_ + col] + bj;

        float sc  = (q == 2) ? -2.f : -1.f;
        float e   = __expf(sc * g);
        float num = (q == 2) ? (1.f - e) : 1.f;
        float act = __fdividef(num, 1.f + e);

        float ai = __shfl_sync(0xffffffffu, act, r);
        float af = __shfl_sync(0xffffffffu, act, 8 + r);
        float ag = __shfl_sync(0xffffffffu, act, 16 + r);
        float ao = __shfl_sync(0xffffffffu, act, 24 + r);

        c_st = fmaf(af, c_st, ai * ag);
        float e2 = __expf(-2.f * c_st);
        float th = __fdividef(1.f - e2, 1.f + e2);

        if (q == 0) {
            h_s[p ^ 1][idx] = ao * th;
            ob[t * H_ + idx] = c_st;              // reference emits the CELL state
        }
        p ^= 1;
        asm volatile("bar.sync 1, 256;" ::: "memory");
    }
}

// ---------------------------------------------------------------------------
extern "C" void kernel_launch(void* const* d_in, const int* in_sizes, int n_in,
                              void* d_out, int out_size)
{
    const float* x      = (const float*)d_in[0];
    const float* Wx     = (const float*)d_in[6];
    const float* Wh     = (const float*)d_in[7];
    const float* b_lstm = (const float*)d_in[8];
    float*       out    = (float*)d_out;

    cudaFuncSetAttribute(attn_rnn_tc, cudaFuncAttributeMaxDynamicSharedMemorySize, SMEM_DYN);

    conv_wx_kernel<<<NCH, 256>>>(Wx);
    attn_rnn_tc<<<B_, 512, SMEM_DYN>>>(x, Wh, b_lstm, out);
}